// round 1
// baseline (speedup 1.0000x reference)
#include <cuda_runtime.h>
#include <math.h>

#define NN  50000
#define FINF 64
#define HH  128
#define EE  800000
#define TT  8
#define PP  250000
#define DD  500000
#define GG  20000
#define VV  2000
#define CATW 384

// ---------------- scratch (device globals; no allocation allowed) ----------------
__device__ __align__(16) float  g_feats[(size_t)(TT + 1) * NN * HH];   // 230 MB
__device__ __align__(16) float  g_agg[(size_t)NN * HH];
__device__ __align__(16) float  g_cat[(size_t)PP * CATW];              // 384 MB
__device__ __align__(16) float  g_hidden[(size_t)PP * CATW];           // 384 MB
__device__ float  g_logprob[PP * 2];
__device__ double g_gsum[GG * 2];
__device__ float  g_within[GG * 2];
__device__ int    g_deg[NN];
__device__ float  g_invdeg[NN];
__device__ int    g_rowptr[NN + 1];
__device__ int    g_cursor[NN];
__device__ int    g_csr[EE];
__device__ int    g_vstart[VV];
__device__ float  g_logc[VV];

// ---------------- CSR build ----------------
__global__ void k_count_deg(const int* __restrict__ edge_dst) {
    int e = blockIdx.x * blockDim.x + threadIdx.x;
    if (e < EE) atomicAdd(&g_deg[edge_dst[e]], 1);
}

// single-block inclusive scan over degrees -> rowptr, cursor(=exclusive), invdeg
__global__ void k_scan() {
    __shared__ int warpsum[32];
    __shared__ int s_carry;
    if (threadIdx.x == 0) s_carry = 0;
    __syncthreads();
    int lane = threadIdx.x & 31, w = threadIdx.x >> 5;
    for (int base = 0; base < NN; base += 1024) {
        int i = base + threadIdx.x;
        int v = (i < NN) ? g_deg[i] : 0;
        int s = v;
#pragma unroll
        for (int o = 1; o < 32; o <<= 1) {
            int t = __shfl_up_sync(0xffffffffu, s, o);
            if (lane >= o) s += t;
        }
        if (lane == 31) warpsum[w] = s;
        __syncthreads();
        if (w == 0) {
            int ws = warpsum[lane];
#pragma unroll
            for (int o = 1; o < 32; o <<= 1) {
                int t = __shfl_up_sync(0xffffffffu, ws, o);
                if (lane >= o) ws += t;
            }
            warpsum[lane] = ws;
        }
        __syncthreads();
        int incl = s + (w > 0 ? warpsum[w - 1] : 0) + s_carry;
        if (i < NN) {
            g_rowptr[i + 1] = incl;
            g_cursor[i] = incl - v;  // exclusive prefix = fill cursor start
            g_invdeg[i] = 1.0f / (float)(v > 1 ? v : 1);
            if (i == 0) g_rowptr[0] = 0;
        }
        __syncthreads();
        if (threadIdx.x == 1023) s_carry = incl;
        __syncthreads();
    }
}

__global__ void k_fill(const int* __restrict__ edge_src, const int* __restrict__ edge_dst) {
    int e = blockIdx.x * blockDim.x + threadIdx.x;
    if (e >= EE) return;
    int pos = atomicAdd(&g_cursor[edge_dst[e]], 1);
    g_csr[pos] = edge_src[e];
}

// ---------------- mean aggregation (atomic-free via CSR) ----------------
template <int F>
__global__ void k_aggregate(const float* __restrict__ h) {
    int node = blockIdx.x * blockDim.y + threadIdx.y;
    if (node >= NN) return;
    int f = threadIdx.x;
    int e0 = g_rowptr[node], e1 = g_rowptr[node + 1];
    float s = 0.f;
    for (int e = e0; e < e1; e++) {
        int src = g_csr[e];
        s += h[(size_t)src * F + f];
    }
    g_agg[(size_t)node * F + f] = s * g_invdeg[node];
}

// ---------------- SGEMM: C = act(A1@W1 [+ A2@W2] + bias) ----------------
// BM=128, BN=128, BK=8, 256 threads, 8x8 per thread.
#define BM 128
#define BN 128
#define BKK 8
__global__ __launch_bounds__(256) void k_sgemm_dual(
    const float* __restrict__ A1, int K1,
    const float* __restrict__ A2, int K2,
    const float* __restrict__ W1, const float* __restrict__ W2,
    const float* __restrict__ bias,
    float* __restrict__ C, int M, int NC, int doRelu)
{
    __shared__ __align__(16) float As[BKK][BM];
    __shared__ __align__(16) float Bs[BKK][BN];
    int tid = threadIdx.x;
    int rowBlock = blockIdx.y * BM;
    int colBlock = blockIdx.x * BN;
    int tx = tid & 15, ty = tid >> 4;
    int rowBase = ty * 8, colBase = tx * 8;

    int la_m = tid >> 1;        // 0..127
    int la_k = (tid & 1) * 4;   // 0 / 4
    int lb_k = tid >> 5;        // 0..7
    int lb_n = (tid & 31) * 4;  // 0..124

    float acc[8][8];
#pragma unroll
    for (int i = 0; i < 8; i++)
#pragma unroll
        for (int j = 0; j < 8; j++) acc[i][j] = 0.f;

#pragma unroll 1
    for (int pass = 0; pass < 2; pass++) {
        const float* A = pass ? A2 : A1;
        const float* W = pass ? W2 : W1;
        int K = pass ? K2 : K1;
        if (A == nullptr) continue;
        for (int k0 = 0; k0 < K; k0 += BKK) {
            int gm = rowBlock + la_m;
            float4 av = (gm < M) ? *(const float4*)(A + (size_t)gm * K + k0 + la_k)
                                 : make_float4(0.f, 0.f, 0.f, 0.f);
            As[la_k + 0][la_m] = av.x;
            As[la_k + 1][la_m] = av.y;
            As[la_k + 2][la_m] = av.z;
            As[la_k + 3][la_m] = av.w;
            *(float4*)&Bs[lb_k][lb_n] =
                *(const float4*)(W + (size_t)(k0 + lb_k) * NC + colBlock + lb_n);
            __syncthreads();
#pragma unroll
            for (int k = 0; k < BKK; k++) {
                float ra[8], rb[8];
#pragma unroll
                for (int i = 0; i < 8; i++) ra[i] = As[k][rowBase + i];
#pragma unroll
                for (int j = 0; j < 8; j++) rb[j] = Bs[k][colBase + j];
#pragma unroll
                for (int i = 0; i < 8; i++)
#pragma unroll
                    for (int j = 0; j < 8; j++) acc[i][j] += ra[i] * rb[j];
            }
            __syncthreads();
        }
    }

#pragma unroll
    for (int i = 0; i < 8; i++) {
        int gm = rowBlock + rowBase + i;
        if (gm >= M) continue;
#pragma unroll
        for (int j = 0; j < 8; j++) {
            int gn = colBlock + colBase + j;
            float v = acc[i][j] + bias[gn];
            if (doRelu) v = fmaxf(v, 0.f);
            C[(size_t)gm * NC + gn] = v;
        }
    }
}

// ---------------- gather place/src rows into cat, zero dst section ----------------
__global__ void k_gather(const int* __restrict__ place_idx, const int* __restrict__ src_idx,
                         const int* __restrict__ t_idx) {
    int idx = blockIdx.x * blockDim.x + threadIdx.x;
    if (idx >= PP * HH) return;
    int p = idx >> 7, f = idx & 127;
    int t = t_idx[p];
    size_t fb = (size_t)t * NN * HH;
    size_t cb = (size_t)p * CATW;
    g_cat[cb + f]          = g_feats[fb + (size_t)place_idx[p] * HH + f];
    g_cat[cb + HH + f]     = g_feats[fb + (size_t)src_idx[p] * HH + f];
    g_cat[cb + 2 * HH + f] = 0.f;
}

__global__ void k_scatter_dst(const int* __restrict__ dst_nodes, const int* __restrict__ dst_seg,
                              const int* __restrict__ t_idx) {
    int idx = blockIdx.x * blockDim.x + threadIdx.x;
    if (idx >= DD * HH) return;
    int d = idx >> 7, f = idx & 127;
    int row = dst_seg[d];
    int t = t_idx[row];
    float v = g_feats[((size_t)t * NN + dst_nodes[d]) * HH + f];
    atomicAdd(&g_cat[(size_t)row * CATW + 2 * HH + f], v);
}

// ---------------- logits + log_softmax (warp per row) ----------------
__global__ void k_logits(const float* __restrict__ Wd2, const float* __restrict__ bd2) {
    int warp = (blockIdx.x * blockDim.x + threadIdx.x) >> 5;
    int lane = threadIdx.x & 31;
    if (warp >= PP) return;
    const float* hrow = g_hidden + (size_t)warp * CATW;
    float a0 = 0.f, a1 = 0.f;
    for (int k = lane; k < CATW; k += 32) {
        float hv = hrow[k];
        a0 += hv * __ldg(&Wd2[k * 2]);
        a1 += hv * __ldg(&Wd2[k * 2 + 1]);
    }
#pragma unroll
    for (int o = 16; o; o >>= 1) {
        a0 += __shfl_down_sync(0xffffffffu, a0, o);
        a1 += __shfl_down_sync(0xffffffffu, a1, o);
    }
    if (lane == 0) {
        a0 += bd2[0];
        a1 += bd2[1];
        float m = fmaxf(a0, a1);
        float lse = m + logf(expf(a0 - m) + expf(a1 - m));
        g_logprob[warp * 2]     = a0 - lse;
        g_logprob[warp * 2 + 1] = a1 - lse;
    }
}

// ---------------- group / variant bookkeeping ----------------
__global__ void k_group_sum(const int* __restrict__ group_id) {
    int p = blockIdx.x * blockDim.x + threadIdx.x;
    if (p >= PP) return;
    int g = group_id[p];
    atomicAdd(&g_gsum[g * 2 + 0], (double)g_logprob[p * 2 + 0]);
    atomicAdd(&g_gsum[g * 2 + 1], (double)g_logprob[p * 2 + 1]);
}

__global__ void k_var_starts(const int* __restrict__ vg) {
    int g = blockIdx.x * blockDim.x + threadIdx.x;
    if (g >= GG) return;
    int v = vg[g];
    if (g == 0 || vg[g - 1] != v) g_vstart[v] = g;
}

// within[g] = inclusive running sum of group sums inside g's variant
// (== cum - var_excl[variant] of the reference, without the 1e5-magnitude cancellation)
__global__ void k_within(const int* __restrict__ vg) {
    int v = blockIdx.x * blockDim.x + threadIdx.x;
    if (v >= VV) return;
    int g = g_vstart[v];
    if (g < 0) return;
    double r0 = 0.0, r1 = 0.0;
    while (g < GG && vg[g] == v) {
        r0 += g_gsum[g * 2];
        r1 += g_gsum[g * 2 + 1];
        g_within[g * 2]     = (float)r0;
        g_within[g * 2 + 1] = (float)r1;
        g++;
    }
}

__global__ void k_logc(const float* __restrict__ counts) {
    __shared__ double red[8];
    double s = 0.0;
    for (int v = threadIdx.x; v < VV; v += blockDim.x) s += (double)counts[v];
#pragma unroll
    for (int o = 16; o; o >>= 1) s += __shfl_down_sync(0xffffffffu, s, o);
    if ((threadIdx.x & 31) == 0) red[threadIdx.x >> 5] = s;
    __syncthreads();
    double tot = 0.0;
#pragma unroll
    for (int i = 0; i < 8; i++) tot += red[i];
    for (int v = threadIdx.x; v < VV; v += blockDim.x)
        g_logc[v] = logf((float)((double)counts[v] / tot));
}

__global__ void k_finalize(const int* __restrict__ group_id, const int* __restrict__ vg,
                           const int* __restrict__ place_idx, float* __restrict__ out) {
    int idx = blockIdx.x * blockDim.x + threadIdx.x;
    if (idx >= PP * 2) return;
    int p = idx >> 1, o = idx & 1;
    int g = group_id[p];
    float add = g_logprob[idx] + g_within[g * 2 + o] + g_logc[vg[g]];
    atomicAdd(&out[place_idx[p] * 2 + o], add);
}

// ---------------- host launch ----------------
extern "C" void kernel_launch(void* const* d_in, const int* in_sizes, int n_in,
                              void* d_out, int out_size) {
    const float* x      = (const float*)d_in[0];
    const float* Wes    = (const float*)d_in[1];
    const float* Wen    = (const float*)d_in[2];
    const float* benc   = (const float*)d_in[3];
    const float* W2s    = (const float*)d_in[4];
    const float* W2n    = (const float*)d_in[5];
    const float* b2     = (const float*)d_in[6];
    const float* Wd1    = (const float*)d_in[7];
    const float* bd1    = (const float*)d_in[8];
    const float* Wd2    = (const float*)d_in[9];
    const float* bd2    = (const float*)d_in[10];
    const float* counts = (const float*)d_in[11];
    const int* edge_src = (const int*)d_in[12];
    const int* edge_dst = (const int*)d_in[13];
    const int* place_idx = (const int*)d_in[14];
    const int* src_idx   = (const int*)d_in[15];
    const int* t_idx     = (const int*)d_in[16];
    const int* dst_nodes = (const int*)d_in[17];
    const int* dst_seg   = (const int*)d_in[18];
    const int* group_id  = (const int*)d_in[19];
    const int* vg        = (const int*)d_in[20];
    float* out = (float*)d_out;

    void *p_deg, *p_gsum, *p_vstart, *p_feats, *p_agg, *p_cat, *p_hidden;
    cudaGetSymbolAddress(&p_deg, g_deg);
    cudaGetSymbolAddress(&p_gsum, g_gsum);
    cudaGetSymbolAddress(&p_vstart, g_vstart);
    cudaGetSymbolAddress(&p_feats, g_feats);
    cudaGetSymbolAddress(&p_agg, g_agg);
    cudaGetSymbolAddress(&p_cat, g_cat);
    cudaGetSymbolAddress(&p_hidden, g_hidden);
    float* feats = (float*)p_feats;
    float* agg   = (float*)p_agg;
    float* cat   = (float*)p_cat;
    float* hid   = (float*)p_hidden;

    // --- CSR build ---
    cudaMemsetAsync(p_deg, 0, NN * sizeof(int));
    k_count_deg<<<(EE + 255) / 256, 256>>>(edge_dst);
    k_scan<<<1, 1024>>>();
    k_fill<<<(EE + 255) / 256, 256>>>(edge_src, edge_dst);

    dim3 gemmGridN(1, (NN + BM - 1) / BM);

    // --- encoder: h0 = relu(x@Wes + agg(x)@Wen + b) ---
    k_aggregate<FINF><<<(NN + 3) / 4, dim3(FINF, 4)>>>(x);
    k_sgemm_dual<<<gemmGridN, 256>>>(x, FINF, agg, FINF, Wes, Wen, benc,
                                     feats, NN, HH, 1);

    // --- T recurrent steps ---
    for (int t = 1; t <= TT; t++) {
        const float* hp = feats + (size_t)(t - 1) * NN * HH;
        float* hn = feats + (size_t)t * NN * HH;
        k_aggregate<HH><<<(NN + 1) / 2, dim3(HH, 2)>>>(hp);
        k_sgemm_dual<<<gemmGridN, 256>>>(hp, HH, agg, HH, W2s, W2n, b2,
                                         hn, NN, HH, 1);
    }

    // --- build cat = [place_f | src_f | dst_f] ---
    k_gather<<<(PP * HH + 255) / 256, 256>>>(place_idx, src_idx, t_idx);
    k_scatter_dst<<<(DD * HH + 255) / 256, 256>>>(dst_nodes, dst_seg, t_idx);

    // --- decoder hidden = relu(cat@Wd1 + bd1) ---
    dim3 gemmGridP(CATW / BN, (PP + BM - 1) / BM);
    k_sgemm_dual<<<gemmGridP, 256>>>(cat, CATW, nullptr, 0, Wd1, nullptr, bd1,
                                     hid, PP, CATW, 1);

    // --- logits + log_softmax ---
    k_logits<<<(PP + 7) / 8, 256>>>(Wd2, bd2);

    // --- group / variant running sums ---
    cudaMemsetAsync(p_gsum, 0, GG * 2 * sizeof(double));
    cudaMemsetAsync(p_vstart, 0xFF, VV * sizeof(int));
    k_group_sum<<<(PP + 255) / 256, 256>>>(group_id);
    k_var_starts<<<(GG + 255) / 256, 256>>>(vg);
    k_logc<<<1, 256>>>(counts);
    k_within<<<(VV + 255) / 256, 256>>>(vg);

    // --- output scatter ---
    cudaMemsetAsync(d_out, 0, (size_t)out_size * sizeof(float));
    k_finalize<<<(PP * 2 + 255) / 256, 256>>>(group_id, vg, place_idx, out);
}